// round 7
// baseline (speedup 1.0000x reference)
#include <cuda_runtime.h>
#include <cuda_bf16.h>
#include <cstdint>
#include <cstring>

#define NTOK 16384
#define HDIM 4096
#define NEXP 64
#define BM   128
#define KC   64
#define XS   (KC + 8)   // x smem row stride (floats)  = 72
#define WS   (KC + 8)   // w smem row stride (bf16)    = 72
#define NCHUNK (HDIM / KC)      // 64
#define SMEM_X_BYTES (2 * BM * XS * 4)            // 73728
#define SMEM_W_BYTES (2 * NEXP * WS * 2)          // 18432 per array
#define SMEM_BYTES   (SMEM_X_BYTES + 2 * SMEM_W_BYTES)  // 110592

#define FLT_MIN_NORMAL 1.17549435e-38f

// Pre-split W (fp32 -> bf16 hi + bf16 lo), lives in L2 (1 MB total).
__device__ __nv_bfloat16 g_w_hi[NEXP * HDIM];
__device__ __nv_bfloat16 g_w_lo[NEXP * HDIM];

__global__ void prep_w_kernel(const float* __restrict__ w) {
    int i = blockIdx.x * blockDim.x + threadIdx.x;
    if (i < NEXP * HDIM) {
        float v = w[i];
        __nv_bfloat16 hi = __float2bfloat16_rn(v);
        float r = v - __bfloat162float(hi);
        g_w_hi[i] = hi;
        g_w_lo[i] = __float2bfloat16_rn(r);
    }
}

__device__ __forceinline__ void mma_bf16(float* c, const uint32_t* a,
                                         uint32_t b0, uint32_t b1) {
    asm volatile(
        "mma.sync.aligned.m16n8k16.row.col.f32.bf16.bf16.f32 "
        "{%0,%1,%2,%3}, {%4,%5,%6,%7}, {%8,%9}, {%0,%1,%2,%3};\n"
        : "+f"(c[0]), "+f"(c[1]), "+f"(c[2]), "+f"(c[3])
        : "r"(a[0]), "r"(a[1]), "r"(a[2]), "r"(a[3]), "r"(b0), "r"(b1));
}

__device__ __forceinline__ void cvt_split(float2 f, uint32_t& hi, uint32_t& lo) {
    __nv_bfloat162 h = __floats2bfloat162_rn(f.x, f.y);
    float rx = f.x - __bfloat162float(h.x);
    float ry = f.y - __bfloat162float(h.y);
    __nv_bfloat162 l = __floats2bfloat162_rn(rx, ry);
    hi = *reinterpret_cast<uint32_t*>(&h);
    lo = *reinterpret_cast<uint32_t*>(&l);
}

// float -> monotone-sortable u32 (works for any sign; d here is <= 0)
__device__ __forceinline__ uint32_t f2sortable(float f) {
    uint32_t b = __float_as_uint(f);
    return b ^ (((int32_t)b >> 31) | 0x80000000u);
}
__device__ __forceinline__ float sortable2f(uint32_t k) {
    uint32_t b = (k & 0x80000000u) ? (k ^ 0x80000000u) : ~k;
    return __uint_as_float(b);
}

__global__ __launch_bounds__(256, 1)
void gate_kernel(const float* __restrict__ x,
                 const float* __restrict__ noise,
                 float* __restrict__ out) {
    extern __shared__ char smem[];
    float* xs = reinterpret_cast<float*>(smem);                       // [2][BM][XS]
    __nv_bfloat16* wh = reinterpret_cast<__nv_bfloat16*>(smem + SMEM_X_BYTES); // [2][NEXP][WS]
    __nv_bfloat16* wl = wh + 2 * NEXP * WS;

    const int tid  = threadIdx.x;
    const int warp = tid >> 5;
    const int lane = tid & 31;
    const int g    = lane >> 2;   // group id (row within 8)
    const int tg   = lane & 3;    // thread in group
    const int mBase = blockIdx.x * BM;

    float acc[8][4];
#pragma unroll
    for (int i = 0; i < 8; i++)
#pragma unroll
        for (int j = 0; j < 4; j++) acc[i][j] = 0.f;

    float4 xr[8];
    uint4  wrh[2], wrl[2];

    auto load_regs = [&](int k0) {
#pragma unroll
        for (int i = 0; i < 8; i++) {
            int idx = tid + i * 256;
            int row = idx >> 4, c4 = idx & 15;
            xr[i] = *reinterpret_cast<const float4*>(
                x + (size_t)(mBase + row) * HDIM + k0 + c4 * 4);
        }
#pragma unroll
        for (int i = 0; i < 2; i++) {
            int idx = tid + i * 256;
            int row = idx >> 3, q = idx & 7;
            wrh[i] = *reinterpret_cast<const uint4*>(
                g_w_hi + (size_t)row * HDIM + k0 + q * 8);
            wrl[i] = *reinterpret_cast<const uint4*>(
                g_w_lo + (size_t)row * HDIM + k0 + q * 8);
        }
    };
    auto store_regs = [&](int buf) {
        float* xb = xs + buf * BM * XS;
#pragma unroll
        for (int i = 0; i < 8; i++) {
            int idx = tid + i * 256;
            int row = idx >> 4, c4 = idx & 15;
            *reinterpret_cast<float4*>(xb + row * XS + c4 * 4) = xr[i];
        }
        __nv_bfloat16* whb = wh + buf * NEXP * WS;
        __nv_bfloat16* wlb = wl + buf * NEXP * WS;
#pragma unroll
        for (int i = 0; i < 2; i++) {
            int idx = tid + i * 256;
            int row = idx >> 3, q = idx & 7;
            *reinterpret_cast<uint4*>(whb + row * WS + q * 8) = wrh[i];
            *reinterpret_cast<uint4*>(wlb + row * WS + q * 8) = wrl[i];
        }
    };

    load_regs(0);
    store_regs(0);
    __syncthreads();

    for (int c = 0; c < NCHUNK; c++) {
        const int buf = c & 1;
        if (c + 1 < NCHUNK) load_regs((c + 1) * KC);

        const float* xb = xs + buf * BM * XS + warp * 16 * XS;
        const __nv_bfloat16* whb = wh + buf * NEXP * WS;
        const __nv_bfloat16* wlb = wl + buf * NEXP * WS;

#pragma unroll
        for (int ks = 0; ks < KC / 16; ks++) {
            const int k0 = ks * 16;
            float2 f00 = *reinterpret_cast<const float2*>(xb + g * XS + k0 + tg * 2);
            float2 f01 = *reinterpret_cast<const float2*>(xb + g * XS + k0 + tg * 2 + 8);
            float2 f10 = *reinterpret_cast<const float2*>(xb + (g + 8) * XS + k0 + tg * 2);
            float2 f11 = *reinterpret_cast<const float2*>(xb + (g + 8) * XS + k0 + tg * 2 + 8);
            uint32_t ah[4], al[4];
            cvt_split(f00, ah[0], al[0]);
            cvt_split(f10, ah[1], al[1]);
            cvt_split(f01, ah[2], al[2]);
            cvt_split(f11, ah[3], al[3]);
#pragma unroll
            for (int nt = 0; nt < 8; nt++) {
                const int e = nt * 8 + g;
                uint32_t bh0 = *reinterpret_cast<const uint32_t*>(whb + e * WS + k0 + tg * 2);
                uint32_t bh1 = *reinterpret_cast<const uint32_t*>(whb + e * WS + k0 + tg * 2 + 8);
                uint32_t bl0 = *reinterpret_cast<const uint32_t*>(wlb + e * WS + k0 + tg * 2);
                uint32_t bl1 = *reinterpret_cast<const uint32_t*>(wlb + e * WS + k0 + tg * 2 + 8);
                mma_bf16(acc[nt], ah, bh0, bh1);   // hi*hi
                mma_bf16(acc[nt], ah, bl0, bl1);   // hi*lo
                mma_bf16(acc[nt], al, bh0, bh1);   // lo*hi
            }
        }
        __syncthreads();
        if (c + 1 < NCHUNK) {
            store_regs(buf ^ 1);
            __syncthreads();
        }
    }

    // ---- epilogue: noise add, then FTZ/DAZ-softmax semantics (XLA:CPU runs
    //      under ScopedFlushDenormal): score = 0 exactly when fl(exp(d))/s
    //      would be subnormal, i.e. exp(d) < FLT_MIN * s. All flushed experts
    //      tie at 0 -> lowest index wins (jax top_k). Above the flush line the
    //      score order is the (strict) order of d itself.
    const int n0 = mBase + warp * 16 + g;
    const int n1 = n0 + 8;
#pragma unroll
    for (int nt = 0; nt < 8; nt++) {
        const int e = nt * 8 + tg * 2;
        float2 nz0 = *reinterpret_cast<const float2*>(noise + (size_t)n0 * NEXP + e);
        float2 nz1 = *reinterpret_cast<const float2*>(noise + (size_t)n1 * NEXP + e);
        acc[nt][0] += nz0.x; acc[nt][1] += nz0.y;
        acc[nt][2] += nz1.x; acc[nt][3] += nz1.y;
    }

#pragma unroll
    for (int r = 0; r < 2; r++) {
        // row max
        float m = -3.4e38f;
#pragma unroll
        for (int nt = 0; nt < 8; nt++) {
#pragma unroll
            for (int jj = 0; jj < 2; jj++)
                m = fmaxf(m, acc[nt][r * 2 + jj]);
        }
#pragma unroll
        for (int mm = 1; mm <= 2; mm <<= 1)
            m = fmaxf(m, __shfl_xor_sync(0xffffffffu, m, mm));

        // denominator
        float dv[16];
        float s = 0.f;
#pragma unroll
        for (int nt = 0; nt < 8; nt++) {
#pragma unroll
            for (int jj = 0; jj < 2; jj++) {
                float d = acc[nt][r * 2 + jj] - m;
                dv[nt * 2 + jj] = d;
                s += __expf(d);
            }
        }
#pragma unroll
        for (int mm = 1; mm <= 2; mm <<= 1)
            s += __shfl_xor_sync(0xffffffffu, s, mm);

        const float flushLim = FLT_MIN_NORMAL * s;  // exp(d) below this -> score flushes to 0

        // u64 keys: (sortable score-order << 32) | (64 - expert)
        unsigned long long k1 = 0ull, k2 = 0ull;
#pragma unroll
        for (int nt = 0; nt < 8; nt++) {
#pragma unroll
            for (int jj = 0; jj < 2; jj++) {
                float d = dv[nt * 2 + jj];
                int   e = nt * 8 + tg * 2 + jj;
                float ed = __expf(d);
                uint32_t k32 = (ed < flushLim) ? 0u : f2sortable(d);
                unsigned long long key =
                    ((unsigned long long)k32 << 32) | (unsigned long long)(64 - e);
                if (key > k1) { k2 = k1; k1 = key; }
                else if (key > k2) { k2 = key; }
            }
        }
#pragma unroll
        for (int mm = 1; mm <= 2; mm <<= 1) {
            unsigned long long o1 = __shfl_xor_sync(0xffffffffu, k1, mm);
            unsigned long long o2 = __shfl_xor_sync(0xffffffffu, k2, mm);
            if (o1 > k1) { k2 = k1; k1 = o1; } else if (o1 > k2) { k2 = o1; }
            if (o2 > k1) { k2 = k1; k1 = o2; } else if (o2 > k2) { k2 = o2; }
        }

        if (tg == 0) {
            const int n = (r == 0) ? n0 : n1;
            int i1 = 64 - (int)(k1 & 0xffffffffull);
            int i2 = 64 - (int)(k2 & 0xffffffffull);
            uint32_t k32_1 = (uint32_t)(k1 >> 32);
            uint32_t k32_2 = (uint32_t)(k2 >> 32);
            float inv = 1.0f / s;
            float w1 = (k32_1 == 0u) ? 0.f : __expf(sortable2f(k32_1)) * inv;
            float w2 = (k32_2 == 0u) ? 0.f : __expf(sortable2f(k32_2)) * inv;
            // layout: [topk_idx as float (N*2)] then [topk_weight (N*2)]
            out[2 * n + 0] = (float)i1;
            out[2 * n + 1] = (float)i2;
            out[2 * NTOK + 2 * n + 0] = w1;
            out[2 * NTOK + 2 * n + 1] = w2;
        }
    }
}

extern "C" void kernel_launch(void* const* d_in, const int* in_sizes, int n_in,
                              void* d_out, int out_size) {
    const float* x     = (const float*)d_in[0];  // hidden_states [4,4096,4096]
    const float* w     = (const float*)d_in[1];  // weight [64,4096]
    const float* noise = (const float*)d_in[2];  // noise [16384,64]
    float* out = (float*)d_out;

    cudaFuncSetAttribute(gate_kernel,
                         cudaFuncAttributeMaxDynamicSharedMemorySize, SMEM_BYTES);

    prep_w_kernel<<<(NEXP * HDIM + 255) / 256, 256>>>(w);
    gate_kernel<<<NTOK / BM, 256, SMEM_BYTES>>>(x, noise, out);
}